// round 9
// baseline (speedup 1.0000x reference)
#include <cuda_runtime.h>
#include <cuda_fp16.h>
#include <math.h>

// SwapV2: Gaussian soft-gather, 3.75-sigma truncated. B=8, C=32, H=W=64 fp32.
// R9: 4-tap LDS.64 chunks (ROWH=68 -> 136B lane stride = bank-optimal for
// 8B accesses, 2 wavefronts/instr) to cut chunk-alignment waste ~16%, plus
// exact tail peel (no speculative row reads). fp16 chunk chains now 2-deep.

#define HH 64
#define WW 64
#define HWP 4096
#define CCN 32
#define SLAB_ROWS 48
#define ROWH 68
#define CROW (CCN * ROWH)
#define NWARPS 32
#define PTILES 9
#define KTRUNC 3.75f
#define LIST_N 464

#define SIN_HALVES (SLAB_ROWS * CCN * ROWH)         // 104448
#define SIN_BYTES  (SIN_HALVES * 2)                 // 208896
#define SW_BYTES   (NWARPS * 256)                   // wy[32]f32 + wx[48]h per warp
#define SMEM_BYTES (SIN_BYTES + SW_BYTES + LIST_N * 4 + 8)

typedef unsigned long long ull;

#define FMA2(d, a, b, c) asm("fma.rn.f32x2 %0, %1, %2, %3;" : "=l"(d) : "l"(a), "l"(b), "l"(c))
#define PACK2(d, lo, hi) asm("mov.b64 %0, {%1, %2};" : "=l"(d) : "f"(lo), "f"(hi))
#define UNPACK2(lo, hi, s) asm("mov.b64 {%0, %1}, %2;" : "=f"(lo), "=f"(hi) : "l"(s))

#define H2(x) (*(const __half2*)&(x))

// per 4-tap chunk: 2-deep fp16 chain -> f32 pair -> FFMA2 with wy
#define CHUNK4(dst, wq, d, wy2) {                                   \
    __half2 _h = __hmul2(H2((wq).x), H2((d).x));                    \
    _h = __hfma2(H2((wq).y), H2((d).y), _h);                        \
    float2 _f = __half22float2(_h);                                 \
    ull _q; PACK2(_q, _f.x, _f.y);                                  \
    FMA2(dst, wy2, _q, dst); }

// row pairs + exact single-row tail (NO speculative reads)
#define BODY(MCH) {                                                 \
    uint2 wxq[MCH];                                                 \
    _Pragma("unroll")                                               \
    for (int j = 0; j < MCH; j++)                                   \
        wxq[j] = *(const uint2*)(s_wxh + 4 * j);                    \
    int t = 0;                                                      \
    for (; t + 1 < wu; t += 2) {                                    \
        float2 wyf = *(const float2*)(s_wy + t);                    \
        ull wyA; PACK2(wyA, wyf.x, wyf.x);                          \
        ull wyB; PACK2(wyB, wyf.y, wyf.y);                          \
        const __half* pa = prow;                                    \
        const __half* pb = prow + CROW;                             \
        _Pragma("unroll")                                           \
        for (int j = 0; j < MCH; j++) {                             \
            uint2 dA = *(const uint2*)(pa + 4 * j);                 \
            uint2 dB = *(const uint2*)(pb + 4 * j);                 \
            CHUNK4(accA, wxq[j], dA, wyA);                          \
            CHUNK4(accB, wxq[j], dB, wyB);                          \
        }                                                           \
        prow += 2 * CROW;                                           \
    }                                                               \
    if (t < wu) {                                                   \
        float wyt = s_wy[t];                                        \
        ull wyA; PACK2(wyA, wyt, wyt);                              \
        _Pragma("unroll")                                           \
        for (int j = 0; j < MCH; j++) {                             \
            uint2 dA = *(const uint2*)(prow + 4 * j);               \
            CHUNK4(accA, wxq[j], dA, wyA);                          \
        }                                                           \
    } }

__global__ __launch_bounds__(1024, 1)
void swapv2_kernel(const float* __restrict__ inp,
                   const float* __restrict__ exPx,
                   const float* __restrict__ exPy,
                   const float* __restrict__ sigx,
                   const float* __restrict__ sigy,
                   float* __restrict__ out)
{
    extern __shared__ char smem[];
    __half* s_in  = (__half*)smem;                          // [48][32][ROWH]
    char*   s_wb  = smem + SIN_BYTES;                       // per-warp 256B
    int*    s_list = (int*)(smem + SIN_BYTES + SW_BYTES);
    int*    s_cnt  = s_list + LIST_N;

    const int tid  = threadIdx.x;
    const int w    = tid >> 5;
    const int lane = tid & 31;
    const int tile = blockIdx.x;                            // 0..8
    const int slab = blockIdx.y;                            // 0..1
    const int b    = blockIdx.z;                            // 0..7
    const int ubase = slab * 16;

    if (tid < 2) s_cnt[tid] = 0;
    __syncthreads();

    const int pbeg = (HWP * tile) / PTILES;
    const int pend = (HWP * (tile + 1)) / PTILES;

    // ---- build pixel list (slab membership) ----
    for (int p = pbeg + tid; p < pend; p += 1024) {
        int idx = b * HWP + p;
        float ey = exPy[idx], sy = sigy[idx];
        int u0 = max(0,      (int)ceilf (ey - KTRUNC * sy));
        int u1 = min(HH - 1, (int)floorf(ey + KTRUNC * sy));
        int ms = (u1 <= 47 && (u0 < 16 || ey < 31.5f)) ? 0 : 1;
        if (ms == slab) s_list[atomicAdd(&s_cnt[0], 1)] = p;
    }

    // ---- stage 48-row fp16 slab as uint2 (4-half) units, pads zeroed ----
    {
        const float* gsrc = inp + (size_t)b * CCN * HWP;
        for (int j = tid; j < SLAB_ROWS * CCN * 17; j += 1024) {
            int q = j % 17;                    // 4-half unit (16 = pad)
            int r = j / 17;                    // r = u*32 + c
            uint2 st = make_uint2(0u, 0u);
            if (q < 16) {
                int u = r >> 5, c = r & 31;
                float4 a = *(const float4*)(gsrc + (size_t)c * HWP
                                            + (ubase + u) * WW + 4 * q);
                __half2 h0 = __float22half2_rn(make_float2(a.x, a.y));
                __half2 h1 = __float22half2_rn(make_float2(a.z, a.w));
                st.x = *(unsigned*)&h0;
                st.y = *(unsigned*)&h1;
            }
            *(uint2*)(s_in + r * ROWH + 4 * q) = st;
        }
    }
    __syncthreads();

    const int cnt = s_cnt[0];
    float*  s_wy  = (float*)(s_wb + w * 256);               // 32 f32
    __half* s_wxh = (__half*)(s_wb + w * 256 + 128);        // 48 halves

    // ---- dynamic work queue ----
    for (;;) {
        int k = 0;
        if (lane == 0) k = atomicAdd(&s_cnt[1], 1);
        k = __shfl_sync(0xFFFFFFFFu, k, 0);
        if (k >= cnt) break;
        const int p = s_list[k];
        const int idx = b * HWP + p;

        float ey = exPy[idx], sy = sigy[idx];
        float ex = exPx[idx], sx = sigx[idx];

        int u0 = max(0,      (int)ceilf (ey - KTRUNC * sy));
        int u1 = min(HH - 1, (int)floorf(ey + KTRUNC * sy));
        int v0 = max(0,      (int)ceilf (ex - KTRUNC * sx));
        int v1 = min(WW - 1, (int)floorf(ex + KTRUNC * sx));
        int v0a = v0 & ~3;                          // 8B-aligned window start

        float invsy = 1.0f / sy, invsx = 1.0f / sx;
        int uu = u0 + lane;
        float dy = ((float)uu - ey) * invsy;
        float wy = (uu <= u1) ? __expf(-0.5f * dy * dy) : 0.0f;
        int vv = v0 + lane;
        float dx = ((float)vv - ex) * invsx;
        float wxf = (vv <= v1) ? __expf(-0.5f * dx * dx) : 0.0f;
        __half wxh = __float2half_rn(wxf);
        float wxr = __half2float(wxh);       // Z must match fp16 weights

        float sumy = wy, sumx = wxr;
        #pragma unroll
        for (int o = 16; o; o >>= 1) {
            sumy += __shfl_xor_sync(0xFFFFFFFFu, sumy, o);
            sumx += __shfl_xor_sync(0xFFFFFFFFu, sumx, o);
        }
        float invZ = 1.0f / (sumy * sumx + 1e-8f);

        s_wy[lane] = wy;
        if (lane < 24) ((unsigned*)s_wxh)[lane] = 0u;
        __syncwarp();
        if (lane <= v1 - v0) s_wxh[(v0 - v0a) + lane] = wxh;
        __syncwarp();

        const int wu  = u1 - u0 + 1;                 // <= 23
        const int mch = ((v1 - v0a) >> 2) + 1;       // 4-tap chunks, <= 7

        const __half* prow = s_in + ((u0 - ubase) * CCN + lane) * ROWH + v0a;
        ull accA = 0ULL, accB = 0ULL;

        switch (mch) {
            case 1: BODY(1); break;
            case 2: BODY(2); break;
            case 3: BODY(3); break;
            case 4: BODY(4); break;
            case 5: BODY(5); break;
            case 6: BODY(6); break;
            default: BODY(7); break;
        }

        float a0, a1, b0, b1;
        UNPACK2(a0, a1, accA);
        UNPACK2(b0, b1, accB);
        out[(size_t)(b * CCN + lane) * HWP + p] = (a0 + a1 + b0 + b1) * invZ;
        __syncwarp();
    }
}

extern "C" void kernel_launch(void* const* d_in, const int* in_sizes, int n_in,
                              void* d_out, int out_size) {
    (void)in_sizes; (void)n_in; (void)out_size;
    const float* inp  = (const float*)d_in[0];
    const float* exPx = (const float*)d_in[1];
    const float* exPy = (const float*)d_in[2];
    const float* sigx = (const float*)d_in[3];
    const float* sigy = (const float*)d_in[4];
    float* out = (float*)d_out;

    cudaFuncSetAttribute(swapv2_kernel,
                         cudaFuncAttributeMaxDynamicSharedMemorySize, SMEM_BYTES);
    dim3 grid(PTILES, 2, 8);          // 144 blocks = one full wave
    swapv2_kernel<<<grid, 1024, SMEM_BYTES>>>(inp, exPx, exPy, sigx, sigy, out);
}

// round 10
// speedup vs baseline: 1.5583x; 1.5583x over previous
#include <cuda_runtime.h>
#include <cuda_fp16.h>
#include <math.h>

// SwapV2: Gaussian soft-gather, 3.75-sigma truncated. B=8, C=32, H=W=64 fp32.
// R10: R8 structure (LDS.128 8-tap chunks, ROWH=72) +
//  (a) 4-way split fp32 accumulators (break FFMA2 dependency chains),
//  (b) software-pipelined pixel setup (prefetch next pixel's queue slot and
//      ex/ey/sigma scalars so the LDG latency hides under the current loop).

#define HH 64
#define WW 64
#define HWP 4096
#define CCN 32
#define SLAB_ROWS 48
#define ROWH 72
#define CROW (CCN * ROWH)
#define NWARPS 32
#define PTILES 9
#define KTRUNC 3.75f
#define LIST_N 464

#define SIN_HALVES (SLAB_ROWS * CCN * ROWH)
#define SIN_BYTES  (SIN_HALVES * 2)                 // 221184
#define SW_BYTES   (NWARPS * 256)                   // wy[32]f32 + wx[48]h per warp
#define SMEM_BYTES (SIN_BYTES + SW_BYTES + LIST_N * 4 + 8)

typedef unsigned long long ull;

#define FMA2(d, a, b, c) asm("fma.rn.f32x2 %0, %1, %2, %3;" : "=l"(d) : "l"(a), "l"(b), "l"(c))
#define PACK2(d, lo, hi) asm("mov.b64 %0, {%1, %2};" : "=l"(d) : "f"(lo), "f"(hi))
#define UNPACK2(lo, hi, s) asm("mov.b64 {%0, %1}, %2;" : "=f"(lo), "=f"(hi) : "l"(s))

#define H2(x) (*(const __half2*)&(x))

// per 8-tap chunk: 4-deep fp16 chain -> f32 pair -> FFMA2 into dst
#define CHUNK(dst, wq, d, wy2) {                                    \
    __half2 _h = __hmul2(H2((wq).x), H2((d).x));                    \
    _h = __hfma2(H2((wq).y), H2((d).y), _h);                        \
    _h = __hfma2(H2((wq).z), H2((d).z), _h);                        \
    _h = __hfma2(H2((wq).w), H2((d).w), _h);                        \
    float2 _f = __half22float2(_h);                                 \
    ull _q; PACK2(_q, _f.x, _f.y);                                  \
    FMA2(dst, wy2, _q, dst); }

// 2-row unrolled body; chunk j alternates accumulators by parity
#define BODY2(MCH) {                                                \
    uint4 wxq[MCH];                                                 \
    _Pragma("unroll")                                               \
    for (int j = 0; j < MCH; j++)                                   \
        wxq[j] = *(const uint4*)(s_wxh + 8 * j);                    \
    for (int t = 0; t < wu; t += 2) {                               \
        float2 wyf = *(const float2*)(s_wy + t);                    \
        ull wyA; PACK2(wyA, wyf.x, wyf.x);                          \
        ull wyB; PACK2(wyB, wyf.y, wyf.y);                          \
        const __half* pa = prow;                                    \
        const __half* pb = (t + 1 < wu) ? prow + CROW : prow;       \
        _Pragma("unroll")                                           \
        for (int j = 0; j < MCH; j++) {                             \
            uint4 dA = *(const uint4*)(pa + 8 * j);                 \
            uint4 dB = *(const uint4*)(pb + 8 * j);                 \
            if (j & 1) { CHUNK(accA1, wxq[j], dA, wyA);             \
                         CHUNK(accB1, wxq[j], dB, wyB); }           \
            else       { CHUNK(accA0, wxq[j], dA, wyA);             \
                         CHUNK(accB0, wxq[j], dB, wyB); }           \
        }                                                           \
        prow += 2 * CROW;                                           \
    } }

// 4-row unrolled body for narrow windows; rows spread over all 4 accs
#define BODY4(MCH) {                                                \
    uint4 wxq[MCH];                                                 \
    _Pragma("unroll")                                               \
    for (int j = 0; j < MCH; j++)                                   \
        wxq[j] = *(const uint4*)(s_wxh + 8 * j);                    \
    for (int t = 0; t < wu; t += 4) {                               \
        float4 wyf = *(const float4*)(s_wy + t);                    \
        ull wyA; PACK2(wyA, wyf.x, wyf.x);                          \
        ull wyB; PACK2(wyB, wyf.y, wyf.y);                          \
        ull wyC; PACK2(wyC, wyf.z, wyf.z);                          \
        ull wyD; PACK2(wyD, wyf.w, wyf.w);                          \
        const __half* pa = prow;                                    \
        const __half* pb = (t + 1 < wu) ? prow + CROW : prow;       \
        const __half* pc = (t + 2 < wu) ? prow + 2 * CROW : prow;   \
        const __half* pd = (t + 3 < wu) ? prow + 3 * CROW : prow;   \
        _Pragma("unroll")                                           \
        for (int j = 0; j < MCH; j++) {                             \
            uint4 dA = *(const uint4*)(pa + 8 * j);                 \
            uint4 dB = *(const uint4*)(pb + 8 * j);                 \
            uint4 dC = *(const uint4*)(pc + 8 * j);                 \
            uint4 dD = *(const uint4*)(pd + 8 * j);                 \
            CHUNK(accA0, wxq[j], dA, wyA);                          \
            CHUNK(accB0, wxq[j], dB, wyB);                          \
            CHUNK(accA1, wxq[j], dC, wyC);                          \
            CHUNK(accB1, wxq[j], dD, wyD);                          \
        }                                                           \
        prow += 4 * CROW;                                           \
    } }

__global__ __launch_bounds__(1024, 1)
void swapv2_kernel(const float* __restrict__ inp,
                   const float* __restrict__ exPx,
                   const float* __restrict__ exPy,
                   const float* __restrict__ sigx,
                   const float* __restrict__ sigy,
                   float* __restrict__ out)
{
    extern __shared__ char smem[];
    __half* s_in  = (__half*)smem;                          // [48][32][ROWH]
    char*   s_wb  = smem + SIN_BYTES;                       // per-warp 256B
    int*    s_list = (int*)(smem + SIN_BYTES + SW_BYTES);
    int*    s_cnt  = s_list + LIST_N;

    const int tid  = threadIdx.x;
    const int w    = tid >> 5;
    const int lane = tid & 31;
    const int tile = blockIdx.x;                            // 0..8
    const int slab = blockIdx.y;                            // 0..1
    const int b    = blockIdx.z;                            // 0..7
    const int ubase = slab * 16;

    if (tid < 2) s_cnt[tid] = 0;
    __syncthreads();

    const int pbeg = (HWP * tile) / PTILES;
    const int pend = (HWP * (tile + 1)) / PTILES;

    // ---- build pixel list (slab membership) ----
    for (int p = pbeg + tid; p < pend; p += 1024) {
        int idx = b * HWP + p;
        float ey = exPy[idx], sy = sigy[idx];
        int u0 = max(0,      (int)ceilf (ey - KTRUNC * sy));
        int u1 = min(HH - 1, (int)floorf(ey + KTRUNC * sy));
        int ms = (u1 <= 47 && (u0 < 16 || ey < 31.5f)) ? 0 : 1;
        if (ms == slab) s_list[atomicAdd(&s_cnt[0], 1)] = p;
    }

    // ---- stage 48-row fp16 slab, pads zeroed ----
    {
        const float* gsrc = inp + (size_t)b * CCN * HWP;
        for (int j = tid; j < SLAB_ROWS * CCN * 9; j += 1024) {
            int q = j % 9;
            int r = j / 9;
            uint4 st = make_uint4(0u, 0u, 0u, 0u);
            if (q < 8) {
                int u = r >> 5, c = r & 31;
                const float* g = gsrc + (size_t)c * HWP + (ubase + u) * WW + 8 * q;
                float4 a = *(const float4*)g;
                float4 bb = *(const float4*)(g + 4);
                __half2 h0 = __float22half2_rn(make_float2(a.x, a.y));
                __half2 h1 = __float22half2_rn(make_float2(a.z, a.w));
                __half2 h2 = __float22half2_rn(make_float2(bb.x, bb.y));
                __half2 h3 = __float22half2_rn(make_float2(bb.z, bb.w));
                st.x = *(unsigned*)&h0; st.y = *(unsigned*)&h1;
                st.z = *(unsigned*)&h2; st.w = *(unsigned*)&h3;
            }
            *(uint4*)(s_in + r * ROWH + 8 * q) = st;
        }
    }
    __syncthreads();

    const int cnt = s_cnt[0];
    float*  s_wy  = (float*)(s_wb + w * 256);               // 32 f32
    __half* s_wxh = (__half*)(s_wb + w * 256 + 128);        // 48 halves

    // ---- software-pipelined work queue ----
    int k = 0;
    if (lane == 0) k = atomicAdd(&s_cnt[1], 1);
    k = __shfl_sync(0xFFFFFFFFu, k, 0);
    bool valid = k < cnt;
    int p = 0; float ey = 0.f, ex = 0.f, sy = 1.f, sx = 1.f;
    if (valid) {
        p = s_list[k];
        int idx = b * HWP + p;
        ey = exPy[idx]; ex = exPx[idx]; sy = sigy[idx]; sx = sigx[idx];
    }

    while (valid) {
        // --- prefetch next pixel's slot + scalars (hides atomic+LDS+LDG) ---
        int k2 = 0;
        if (lane == 0) k2 = atomicAdd(&s_cnt[1], 1);
        k2 = __shfl_sync(0xFFFFFFFFu, k2, 0);
        bool valid2 = k2 < cnt;
        int p2 = 0; float ey2 = 0.f, ex2 = 0.f, sy2 = 1.f, sx2 = 1.f;
        if (valid2) {
            p2 = s_list[k2];
            int idx2 = b * HWP + p2;
            ey2 = exPy[idx2]; ex2 = exPx[idx2];
            sy2 = sigy[idx2]; sx2 = sigx[idx2];
        }

        // --- process current pixel ---
        int u0 = max(0,      (int)ceilf (ey - KTRUNC * sy));
        int u1 = min(HH - 1, (int)floorf(ey + KTRUNC * sy));
        int v0 = max(0,      (int)ceilf (ex - KTRUNC * sx));
        int v1 = min(WW - 1, (int)floorf(ex + KTRUNC * sx));
        int v0a = v0 & ~7;

        float invsy = 1.0f / sy, invsx = 1.0f / sx;
        int uu = u0 + lane;
        float dy = ((float)uu - ey) * invsy;
        float wy = (uu <= u1) ? __expf(-0.5f * dy * dy) : 0.0f;
        int vv = v0 + lane;
        float dx = ((float)vv - ex) * invsx;
        float wxf = (vv <= v1) ? __expf(-0.5f * dx * dx) : 0.0f;
        __half wxh = __float2half_rn(wxf);
        float wxr = __half2float(wxh);       // Z must match fp16 weights

        float sumy = wy, sumx = wxr;
        #pragma unroll
        for (int o = 16; o; o >>= 1) {
            sumy += __shfl_xor_sync(0xFFFFFFFFu, sumy, o);
            sumx += __shfl_xor_sync(0xFFFFFFFFu, sumx, o);
        }
        float invZ = 1.0f / (sumy * sumx + 1e-8f);

        s_wy[lane] = wy;
        if (lane < 24) ((unsigned*)s_wxh)[lane] = 0u;
        __syncwarp();
        if (lane <= v1 - v0) s_wxh[(v0 - v0a) + lane] = wxh;
        __syncwarp();

        const int wu  = u1 - u0 + 1;                 // <= 23
        const int mch = ((v1 - v0a) >> 3) + 1;       // <= 4

        const __half* prow = s_in + ((u0 - ubase) * CCN + lane) * ROWH + v0a;
        ull accA0 = 0ULL, accA1 = 0ULL, accB0 = 0ULL, accB1 = 0ULL;

        switch (mch) {
            case 1: BODY4(1); break;
            case 2: BODY4(2); break;
            case 3: BODY2(3); break;
            case 4: BODY2(4); break;
            default: BODY2(5); break;
        }

        float a0, a1, b0, b1, c0, c1, d0, d1;
        UNPACK2(a0, a1, accA0);
        UNPACK2(b0, b1, accA1);
        UNPACK2(c0, c1, accB0);
        UNPACK2(d0, d1, accB1);
        out[(size_t)(b * CCN + lane) * HWP + p] =
            ((a0 + a1) + (b0 + b1) + ((c0 + c1) + (d0 + d1))) * invZ;
        __syncwarp();

        // --- rotate pipeline ---
        k = k2; p = p2; valid = valid2;
        ey = ey2; ex = ex2; sy = sy2; sx = sx2;
    }
}

extern "C" void kernel_launch(void* const* d_in, const int* in_sizes, int n_in,
                              void* d_out, int out_size) {
    (void)in_sizes; (void)n_in; (void)out_size;
    const float* inp  = (const float*)d_in[0];
    const float* exPx = (const float*)d_in[1];
    const float* exPy = (const float*)d_in[2];
    const float* sigx = (const float*)d_in[3];
    const float* sigy = (const float*)d_in[4];
    float* out = (float*)d_out;

    cudaFuncSetAttribute(swapv2_kernel,
                         cudaFuncAttributeMaxDynamicSharedMemorySize, SMEM_BYTES);
    dim3 grid(PTILES, 2, 8);          // 144 blocks = one full wave
    swapv2_kernel<<<grid, 1024, SMEM_BYTES>>>(inp, exPx, exPy, sigx, sigy, out);
}